// round 15
// baseline (speedup 1.0000x reference)
#include <cuda_runtime.h>
#include <cuda_bf16.h>
#include <cstdint>

#define BINS 32
#define CZ   128
#define NCLS 66              // 2*BINS + 2
#define LSEQ 768
#define NB   2
#define TPB  1024            // 32 warps, one CTA per SM
#define NCTAS 148
#define JCHUNK 32            // j-vectors per chunk = 32*512B = 16KB
#define CPR   (LSEQ / JCHUNK)                  // 24 chunks per row
#define CHUNK_FLOATS (JCHUNK * CZ)             // 4096 floats
#define CHUNK_BYTES  (CHUNK_FLOATS * 4)        // 16384
#define NCHUNK (NB * LSEQ * CPR)               // 36864
#define NBUF 2               // double buffer: exactly 1 drain overlaps compute

// dynamic smem layout (bytes):
//   [0, 33792)             wb  (66*128 floats; row 0 = zeros = mask sink)
//   [33792, +2*16KB)       stage[2] double buffer
//   then rj (1536 ints), mj (1536 bytes)
#define OFF_WB    0
#define OFF_STAGE 33792
#define OFF_RJ    (OFF_STAGE + NBUF * CHUNK_BYTES)
#define OFF_MJ    (OFF_RJ + NB * LSEQ * 4)
#define SMEM_TOTAL (OFF_MJ + NB * LSEQ)        // ~70KB

// Double-buffered bulk-store kernel, 16KB chunks. Chunk-size scan (profiled):
// 64KB=95.5us, 48KB=90.8us, 32KB=86.5us -> finer chunks shrink the serial
// barrier quantum and keep the TMA write queue continuously fed. NBUF=2 keeps
// exactly one TMA smem-read drain concurrent with compute (NBUF=3 = -40%).
__global__ __launch_bounds__(TPB) void relpos_kernel(
    const int*   __restrict__ ridx,
    const int*   __restrict__ rmask,
    const float* __restrict__ W,
    const float* __restrict__ bias,
    float*       __restrict__ out)
{
    extern __shared__ char smem[];
    float*         wb    = reinterpret_cast<float*>(smem + OFF_WB);
    float*         stage = reinterpret_cast<float*>(smem + OFF_STAGE);
    int*           rj    = reinterpret_cast<int*>(smem + OFF_RJ);
    unsigned char* mj    = reinterpret_cast<unsigned char*>(smem + OFF_MJ);

    const int tid = threadIdx.x;

    #pragma unroll 2
    for (int k = tid; k < NCLS * CZ; k += TPB)
        wb[k] = (k < CZ) ? 0.0f : (W[k] + bias[k & (CZ - 1)]);

    for (int k = tid; k < NB * LSEQ; k += TPB) {
        rj[k] = ridx[k];
        mj[k] = (unsigned char)(rmask[k] != 0);
    }
    __syncthreads();

    const int lane = tid & 31;
    const int warp = tid >> 5;

    uint32_t stage_u32;
    asm("{ .reg .u64 t; cvta.to.shared.u64 t, %1; cvt.u32.u64 %0, t; }"
        : "=r"(stage_u32) : "l"(stage));

    int it = 0;
    for (int c = blockIdx.x; c < NCHUNK; c += NCTAS, it++) {
        const int buf = it & 1;
        float4* sbuf = reinterpret_cast<float4*>(stage + buf * CHUNK_FLOATS);

        // Before overwriting this buffer, ensure the bulk store issued two
        // iterations ago (which read it) has finished its smem reads.
        if (it >= NBUF && tid == 0)
            asm volatile("cp.async.bulk.wait_group.read %0;" :: "n"(NBUF - 1)
                         : "memory");
        __syncthreads();

        const int row   = c / CPR;              // 0 .. B*L-1
        const int jbase = (c - row * CPR) * JCHUNK;
        const int b     = row / LSEQ;
        const int i     = row - b * LSEQ;
        const int boff  = b * LSEQ;
        const int ri    = rj[boff + i];
        const bool mi   = (mj[boff + i] != 0);

        // 32 j's / 32 warps = exactly 1 per warp
        {
            const int j = jbase + warp;
            int d = rj[boff + j] - ri;
            d = min(max(d, -BINS), BINS) + BINS + 1;      // [1, 65]
            if (!(mi && (mj[boff + j] != 0))) d = 0;      // masked -> zero row
            float4 v = *reinterpret_cast<const float4*>(&wb[d * CZ + lane * 4]);
            sbuf[warp * 32 + lane] = v;
        }
        __syncthreads();

        if (tid == 0) {
            asm volatile("fence.proxy.async.shared::cta;" ::: "memory");
            const float* dst = out + (size_t)row * LSEQ * CZ + (size_t)jbase * CZ;
            asm volatile(
                "cp.async.bulk.global.shared::cta.bulk_group [%0], [%1], %2;"
                :: "l"(dst), "r"(stage_u32 + buf * CHUNK_BYTES), "n"(CHUNK_BYTES)
                : "memory");
            asm volatile("cp.async.bulk.commit_group;" ::: "memory");
        }
    }

    // Drain all outstanding bulk stores before exit.
    if (tid == 0)
        asm volatile("cp.async.bulk.wait_group 0;" ::: "memory");
}

extern "C" void kernel_launch(void* const* d_in, const int* in_sizes, int n_in,
                              void* d_out, int out_size) {
    const int*   ridx  = (const int*)d_in[0];
    const int*   rmask = (const int*)d_in[1];
    const float* W     = (const float*)d_in[2];
    const float* bias  = (const float*)d_in[3];
    float*       out   = (float*)d_out;

    static int configured = 0;
    if (!configured) {
        cudaFuncSetAttribute(relpos_kernel,
                             cudaFuncAttributeMaxDynamicSharedMemorySize,
                             SMEM_TOTAL);
        configured = 1;
    }
    relpos_kernel<<<NCTAS, TPB, SMEM_TOTAL>>>(ridx, rmask, W, bias, out);
}

// round 16
// speedup vs baseline: 1.0553x; 1.0553x over previous
#include <cuda_runtime.h>
#include <cuda_bf16.h>
#include <cstdint>

#define BINS 32
#define CZ   128
#define NCLS 66              // 2*BINS + 2
#define LSEQ 768
#define NB   2
#define TPB  512             // 16 warps; 2 CTAs per SM alternate
#define NCTAS 296
#define JCHUNK 64            // j-vectors per chunk = 64*512B = 32KB (optimum)
#define CPR   (LSEQ / JCHUNK)                  // 12 chunks per row
#define CHUNK_FLOATS (JCHUNK * CZ)             // 8192 floats
#define CHUNK_BYTES  (CHUNK_FLOATS * 4)        // 32768
#define NCHUNK (NB * LSEQ * CPR)               // 18432
#define NBUF 2               // double buffer: exactly 1 drain overlaps compute

// dynamic smem layout (bytes):
//   [0, 33792)             wb  (66*128 floats; row 0 = zeros = mask sink)
//   [33792, +2*32KB)       stage[2] double buffer
//   then rj (1536 ints), mj (1536 bytes)
#define OFF_WB    0
#define OFF_STAGE 33792
#define OFF_RJ    (OFF_STAGE + NBUF * CHUNK_BYTES)
#define OFF_MJ    (OFF_RJ + NB * LSEQ * 4)
#define SMEM_TOTAL (OFF_MJ + NB * LSEQ)        // 107008 B -> 2 CTAs/SM

// 2-CTA/SM double-buffered bulk-store kernel, 32KB chunks (scan optimum:
// 64K=95.5, 48K=90.8, 32K=86.5, 16K=106.2 us profiled). While one CTA sits in
// its barrier+fence+issue phase, the co-resident CTA computes and drains —
// cross-CTA overlap hides the serial quantum that killed the 16KB variant.
__global__ __launch_bounds__(TPB) void relpos_kernel(
    const int*   __restrict__ ridx,
    const int*   __restrict__ rmask,
    const float* __restrict__ W,
    const float* __restrict__ bias,
    float*       __restrict__ out)
{
    extern __shared__ char smem[];
    float*         wb    = reinterpret_cast<float*>(smem + OFF_WB);
    float*         stage = reinterpret_cast<float*>(smem + OFF_STAGE);
    int*           rj    = reinterpret_cast<int*>(smem + OFF_RJ);
    unsigned char* mj    = reinterpret_cast<unsigned char*>(smem + OFF_MJ);

    const int tid = threadIdx.x;

    #pragma unroll 4
    for (int k = tid; k < NCLS * CZ; k += TPB)
        wb[k] = (k < CZ) ? 0.0f : (W[k] + bias[k & (CZ - 1)]);

    for (int k = tid; k < NB * LSEQ; k += TPB) {
        rj[k] = ridx[k];
        mj[k] = (unsigned char)(rmask[k] != 0);
    }
    __syncthreads();

    const int lane = tid & 31;
    const int warp = tid >> 5;

    uint32_t stage_u32;
    asm("{ .reg .u64 t; cvta.to.shared.u64 t, %1; cvt.u32.u64 %0, t; }"
        : "=r"(stage_u32) : "l"(stage));

    int it = 0;
    for (int c = blockIdx.x; c < NCHUNK; c += NCTAS, it++) {
        const int buf = it & 1;
        float4* sbuf = reinterpret_cast<float4*>(stage + buf * CHUNK_FLOATS);

        // Before overwriting this buffer, ensure the bulk store issued two
        // iterations ago (which read it) has finished its smem reads.
        if (it >= NBUF && tid == 0)
            asm volatile("cp.async.bulk.wait_group.read %0;" :: "n"(NBUF - 1)
                         : "memory");
        __syncthreads();

        const int row   = c / CPR;              // 0 .. B*L-1
        const int jbase = (c - row * CPR) * JCHUNK;
        const int b     = row / LSEQ;
        const int i     = row - b * LSEQ;
        const int boff  = b * LSEQ;
        const int ri    = rj[boff + i];
        const bool mi   = (mj[boff + i] != 0);

        // 64 j's / 16 warps = 4 per warp; write into staging buffer
        #pragma unroll 4
        for (int t = warp; t < JCHUNK; t += TPB / 32) {
            const int j = jbase + t;
            int d = rj[boff + j] - ri;
            d = min(max(d, -BINS), BINS) + BINS + 1;      // [1, 65]
            if (!(mi && (mj[boff + j] != 0))) d = 0;      // masked -> zero row
            float4 v = *reinterpret_cast<const float4*>(&wb[d * CZ + lane * 4]);
            sbuf[t * 32 + lane] = v;
        }
        __syncthreads();

        if (tid == 0) {
            asm volatile("fence.proxy.async.shared::cta;" ::: "memory");
            const float* dst = out + (size_t)row * LSEQ * CZ + (size_t)jbase * CZ;
            asm volatile(
                "cp.async.bulk.global.shared::cta.bulk_group [%0], [%1], %2;"
                :: "l"(dst), "r"(stage_u32 + buf * CHUNK_BYTES), "n"(CHUNK_BYTES)
                : "memory");
            asm volatile("cp.async.bulk.commit_group;" ::: "memory");
        }
    }

    // Drain all outstanding bulk stores before exit.
    if (tid == 0)
        asm volatile("cp.async.bulk.wait_group 0;" ::: "memory");
}

extern "C" void kernel_launch(void* const* d_in, const int* in_sizes, int n_in,
                              void* d_out, int out_size) {
    const int*   ridx  = (const int*)d_in[0];
    const int*   rmask = (const int*)d_in[1];
    const float* W     = (const float*)d_in[2];
    const float* bias  = (const float*)d_in[3];
    float*       out   = (float*)d_out;

    static int configured = 0;
    if (!configured) {
        cudaFuncSetAttribute(relpos_kernel,
                             cudaFuncAttributeMaxDynamicSharedMemorySize,
                             SMEM_TOTAL);
        configured = 1;
    }
    relpos_kernel<<<NCTAS, TPB, SMEM_TOTAL>>>(ridx, rmask, W, bias, out);
}

// round 17
// speedup vs baseline: 1.0625x; 1.0068x over previous
#include <cuda_runtime.h>
#include <cuda_bf16.h>
#include <cstdint>

#define BINS 32
#define CZ   128
#define NCLS 66              // 2*BINS + 2
#define LSEQ 768
#define NB   2
#define TPB  1024            // 32 warps, one CTA per SM
#define NCTAS 148
#define JCHUNK 64            // 64 j-vectors = 32KB chunk (scan optimum)
#define CPR   (LSEQ / JCHUNK)                  // 12 chunks per row
#define CHUNK_FLOATS (JCHUNK * CZ)             // 8192 floats
#define CHUNK_BYTES  (CHUNK_FLOATS * 4)        // 32768
#define NCHUNK (NB * LSEQ * CPR)               // 18432
#define NBUF 2

// dynamic smem layout (bytes):
//   wb   [0, 33792)              W+b table, row 0 = zeros (mask sink)
//   rep  [33792, +3*32KB)        rep0 (zeros) / rep1 / rep65 replicated rows
//   stage[+2*32KB)               double buffer for band chunks
//   rj (1536 ints), mj (1536 B), allm (2 ints)
#define OFF_WB    0
#define OFF_REP   33792
#define OFF_STAGE (OFF_REP + 3 * CHUNK_BYTES)
#define OFF_RJ    (OFF_STAGE + NBUF * CHUNK_BYTES)
#define OFF_MJ    (OFF_RJ + NB * LSEQ * 4)
#define OFF_ALLM  (OFF_MJ + NB * LSEQ)
#define SMEM_TOTAL (OFF_ALLM + 2 * 4)          // ~205KB, 1 CTA/SM

// Run-structure kernel: residue_index is sorted, so chunks entirely outside
// the |diff|<32 band are 64 copies of one class vector. Those are serviced by
// a single cp.async.bulk from a prebuilt replicated buffer (no compute, no
// barriers, no waits — issued by tid 32, separate bulk-group stream). Only
// band-straddling / partial-mask chunks take the staged path (tid 0 stream,
// NBUF=2, one drain concurrent with compute).
__global__ __launch_bounds__(TPB) void relpos_kernel(
    const int*   __restrict__ ridx,
    const int*   __restrict__ rmask,
    const float* __restrict__ W,
    const float* __restrict__ bias,
    float*       __restrict__ out)
{
    extern __shared__ char smem[];
    float*         wb    = reinterpret_cast<float*>(smem + OFF_WB);
    float*         rep   = reinterpret_cast<float*>(smem + OFF_REP);
    float*         stage = reinterpret_cast<float*>(smem + OFF_STAGE);
    int*           rj    = reinterpret_cast<int*>(smem + OFF_RJ);
    unsigned char* mj    = reinterpret_cast<unsigned char*>(smem + OFF_MJ);
    int*           allm  = reinterpret_cast<int*>(smem + OFF_ALLM);

    const int tid = threadIdx.x;

    if (tid < 2) allm[tid] = 1;
    __syncthreads();

    #pragma unroll 2
    for (int k = tid; k < NCLS * CZ; k += TPB)
        wb[k] = (k < CZ) ? 0.0f : (W[k] + bias[k & (CZ - 1)]);

    for (int k = tid; k < NB * LSEQ; k += TPB) {
        rj[k] = ridx[k];
        const int m = (rmask[k] != 0);
        mj[k] = (unsigned char)m;
        if (!m) allm[k / LSEQ] = 0;            // race-benign
    }
    __syncthreads();

    // Build replicated buffers from wb: rep0 = zeros, rep1 = row1 x64, rep65 = row65 x64
    for (int k = tid; k < 3 * CHUNK_FLOATS; k += TPB) {
        const int which = k / CHUNK_FLOATS;    // 0,1,2
        const int col   = k & (CZ - 1);
        rep[k] = (which == 0) ? 0.0f : wb[(which == 1 ? 1 : 65) * CZ + col];
    }
    __syncthreads();
    // Make wb/rep visible to the async proxy for both issuing threads.
    if (tid == 0 || tid == 32)
        asm volatile("fence.proxy.async.shared::cta;" ::: "memory");

    const int lane = tid & 31;
    const int warp = tid >> 5;

    uint32_t smem_u32;
    asm("{ .reg .u64 t; cvta.to.shared.u64 t, %1; cvt.u32.u64 %0, t; }"
        : "=r"(smem_u32) : "l"(smem));
    const uint32_t rep_u32   = smem_u32 + OFF_REP;
    const uint32_t stage_u32 = smem_u32 + OFF_STAGE;

    int sit = 0;   // staged-iteration counter (tid0 bulk-group stream)
    for (int c = blockIdx.x; c < NCHUNK; c += NCTAS) {
        const int row   = c / CPR;              // 0 .. B*L-1
        const int jbase = (c - row * CPR) * JCHUNK;
        const int b     = row / LSEQ;
        const int i     = row - b * LSEQ;
        const int boff  = b * LSEQ;
        const int ri    = rj[boff + i];
        const bool mi   = (mj[boff + i] != 0);

        const float* dst = out + (size_t)row * LSEQ * CZ + (size_t)jbase * CZ;

        // Fast-path classification (uniform across CTA: all from smem)
        int fp = -1;
        if (!mi)                                          fp = 0;  // row masked -> zeros
        else if (allm[b]) {
            if      (rj[boff + jbase + JCHUNK - 1] <= ri - BINS) fp = 1;  // d==1 run
            else if (rj[boff + jbase]              >= ri + BINS) fp = 2;  // d==65 run
        }

        if (fp >= 0) {
            if (tid == 32) {
                asm volatile(
                    "cp.async.bulk.global.shared::cta.bulk_group [%0], [%1], %2;"
                    :: "l"(dst), "r"(rep_u32 + fp * CHUNK_BYTES), "n"(CHUNK_BYTES)
                    : "memory");
                asm volatile("cp.async.bulk.commit_group;" ::: "memory");
            }
            continue;                                   // no barrier needed
        }

        // ---- staged path (band chunks / partial masks) ----
        const int buf = sit & 1;
        float4* sbuf = reinterpret_cast<float4*>(stage + buf * CHUNK_FLOATS);

        if (sit >= NBUF && tid == 0)
            asm volatile("cp.async.bulk.wait_group.read %0;" :: "n"(NBUF - 1)
                         : "memory");
        __syncthreads();

        #pragma unroll 2
        for (int t = warp; t < JCHUNK; t += TPB / 32) {
            const int j = jbase + t;
            int d = rj[boff + j] - ri;
            d = min(max(d, -BINS), BINS) + BINS + 1;      // [1, 65]
            if (!(mi && (mj[boff + j] != 0))) d = 0;      // masked -> zero row
            float4 v = *reinterpret_cast<const float4*>(&wb[d * CZ + lane * 4]);
            sbuf[t * 32 + lane] = v;
        }
        __syncthreads();

        if (tid == 0) {
            asm volatile("fence.proxy.async.shared::cta;" ::: "memory");
            asm volatile(
                "cp.async.bulk.global.shared::cta.bulk_group [%0], [%1], %2;"
                :: "l"(dst), "r"(stage_u32 + buf * CHUNK_BYTES), "n"(CHUNK_BYTES)
                : "memory");
            asm volatile("cp.async.bulk.commit_group;" ::: "memory");
        }
        sit++;
    }

    // Drain both bulk-group streams before exit.
    if (tid == 0 || tid == 32)
        asm volatile("cp.async.bulk.wait_group 0;" ::: "memory");
}

extern "C" void kernel_launch(void* const* d_in, const int* in_sizes, int n_in,
                              void* d_out, int out_size) {
    const int*   ridx  = (const int*)d_in[0];
    const int*   rmask = (const int*)d_in[1];
    const float* W     = (const float*)d_in[2];
    const float* bias  = (const float*)d_in[3];
    float*       out   = (float*)d_out;

    static int configured = 0;
    if (!configured) {
        cudaFuncSetAttribute(relpos_kernel,
                             cudaFuncAttributeMaxDynamicSharedMemorySize,
                             SMEM_TOTAL);
        configured = 1;
    }
    relpos_kernel<<<NCTAS, TPB, SMEM_TOTAL>>>(ridx, rmask, W, bias, out);
}